// round 11
// baseline (speedup 1.0000x reference)
#include <cuda_runtime.h>
#include <cuda_fp16.h>
#include <cstdint>

#define N_NODES   50000
#define IN_FEAT   64
#define HIDDEN    128
#define N_EDGES   800000
#define NUM_LAYERS 3
#define NBLK      ((N_NODES + 255) / 256)   // 196
#define HPAIRS    (HIDDEN / 2)              // 64 pairs per row

// ---------------- scratch (device globals; no allocation allowed) ------------
__device__ __align__(128) uint2   g_hpkA[N_NODES * HPAIRS];  // packed h (hi,lo fp16x2)
__device__ __align__(128) uint2   g_hpkB[N_NODES * HPAIRS];
__device__ __align__(128) __half2 g_t16 [N_NODES * HPAIRS];  // t in fp16 pairs
__device__ __align__(128) float   g_z   [N_NODES * HIDDEN];
__device__ int g_cnt   [N_NODES];
__device__ int g_offs  [N_NODES + 1];
__device__ int g_cursor[N_NODES];
__device__ int g_esrc  [N_EDGES];
__device__ int g_is64;
// single-pass scan state (reset by detect_k each call)
__device__ int g_aggr  [NBLK];
__device__ int g_flagA [NBLK];
__device__ int g_prefix[NBLK];
__device__ int g_flagP;
// fp16 fragment-major weights: uint2 {b0,b1}
// W_in: 2048 at 0; Wn[l]: 2048 + l*4096; Ws[l]: 2048 + (3+l)*4096
__device__ __align__(256) uint2 g_w2[2048 + 6 * 4096];

// ---------------- fp16 split helpers -----------------------------------------
__device__ __forceinline__ uint32_t pack_h2(float x, float y) {
    __half2 h = __floats2half2_rn(x, y);
    return *(uint32_t*)&h;
}
// split float2 -> fp16 hi + fp16 residual lo (A = hi + lo to ~22 bits)
__device__ __forceinline__ void split2h(float2 v, uint32_t& hi, uint32_t& lo) {
    __half2 h = __floats2half2_rn(v.x, v.y);
    float2 hf = __half22float2(h);
    __half2 l = __floats2half2_rn(v.x - hf.x, v.y - hf.y);
    hi = *(uint32_t*)&h;
    lo = *(uint32_t*)&l;
}
__device__ __forceinline__ void mma_f16(float* c, const uint32_t* a, uint32_t b0, uint32_t b1) {
    asm volatile(
        "mma.sync.aligned.m16n8k16.row.col.f32.f16.f16.f32 "
        "{%0,%1,%2,%3}, {%4,%5,%6,%7}, {%8,%9}, {%0,%1,%2,%3};"
        : "+f"(c[0]), "+f"(c[1]), "+f"(c[2]), "+f"(c[3])
        : "r"(a[0]), "r"(a[1]), "r"(a[2]), "r"(a[3]), "r"(b0), "r"(b1));
}

// ---------------- index helpers ----------------------------------------------
__device__ __forceinline__ int load_src(const int* ei, int e, int is64) {
    return is64 ? ei[2 * e] : ei[e];
}
__device__ __forceinline__ int load_dst(const int* ei, int e, int is64) {
    return is64 ? ei[2 * (N_EDGES + e)] : ei[N_EDGES + e];
}

// ---------------- dtype detect + per-call state reset ---------------------------
__global__ void detect_k(const int* __restrict__ ei) {
    int lane = threadIdx.x;
    // reset scan flags for this call (graph-replay safe)
    for (int i = lane; i < NBLK; i += 32) g_flagA[i] = 0;
    if (lane == 0) g_flagP = 0;
    int bad = 0;
    for (int i = lane; i < 256; i += 32) bad |= (ei[2 * i + 1] != 0);
    bad = __any_sync(0xFFFFFFFFu, bad);
    if (lane == 0) g_is64 = !bad;
    __threadfence();
}

// ---------------- count ----------------------------------------------------------
__global__ void count_k(const int* __restrict__ ei) {
    int e = blockIdx.x * blockDim.x + threadIdx.x;
    if (e >= N_EDGES) return;
    atomicAdd(&g_cnt[load_dst(ei, e, g_is64)], 1);
}

// ---------------- single-pass scan (all 196 blocks resident; spin-sync) -----------
__global__ __launch_bounds__(256)
void scan_fused_k() {
    __shared__ int sh[256];
    __shared__ int sa[256];
    const int t   = threadIdx.x;
    const int bid = blockIdx.x;
    const int idx = bid * 256 + t;

    int v = (idx < N_NODES) ? g_cnt[idx] : 0;
    sh[t] = v;
    __syncthreads();
    for (int d = 1; d < 256; d <<= 1) {
        int n = (t >= d) ? sh[t - d] : 0;
        __syncthreads();
        sh[t] += n;
        __syncthreads();
    }
    // publish block aggregate
    if (t == 0) {
        g_aggr[bid] = sh[255];
        __threadfence();
        *(volatile int*)&g_flagA[bid] = 1;
    }

    // block 0: wait for all aggregates, scan them, publish prefixes
    if (bid == 0) {
        for (int i = t; i < NBLK; i += 256)
            while (*(volatile int*)&g_flagA[i] == 0) __nanosleep(50);
        __syncthreads();
        int a = 0;
        if (t < NBLK) a = g_aggr[t];
        sa[t] = a;
        __syncthreads();
        for (int d = 1; d < 256; d <<= 1) {
            int n = (t >= d) ? sa[t - d] : 0;
            __syncthreads();
            sa[t] += n;
            __syncthreads();
        }
        if (t < NBLK) g_prefix[t] = sa[t] - a;   // exclusive
        __threadfence();
        __syncthreads();
        if (t == 0) *(volatile int*)&g_flagP = 1;
    }

    // all blocks: wait for prefixes
    if (t == 0)
        while (*(volatile int*)&g_flagP == 0) __nanosleep(50);
    __syncthreads();
    __threadfence();

    int ex = g_prefix[bid] + sh[t] - v;
    if (idx < N_NODES) {
        g_offs[idx]   = ex;
        g_cursor[idx] = ex;
        if (idx == N_NODES - 1) g_offs[N_NODES] = ex + v;
    }
}

// ---------------- CSR fill --------------------------------------------------------
__global__ void fill_k(const int* __restrict__ ei) {
    int e = blockIdx.x * blockDim.x + threadIdx.x;
    if (e >= N_EDGES) return;
    int is64 = g_is64;
    int s = load_src(ei, e, is64);
    int d = load_dst(ei, e, is64);
    g_esrc[atomicAdd(&g_cursor[d], 1)] = s;
}

// ---------------- weight convert: ALL weights in one kernel ------------------------
__global__ void conv_all_k(const float* __restrict__ W_in,
                           const float* __restrict__ W_nbr,
                           const float* __restrict__ W_self) {
    constexpr int TOTAL = 2048 + 6 * 4096;
    for (int idx = blockIdx.x * blockDim.x + threadIdx.x; idx < TOTAL;
         idx += gridDim.x * blockDim.x) {
        const float* W;
        int NSTEP, local;
        if (idx < 2048) {
            W = W_in; NSTEP = 4; local = idx;
        } else {
            int slot = (idx - 2048) / 4096;
            local = (idx - 2048) % 4096;
            NSTEP = 8;
            W = (slot < 3) ? (W_nbr  + (size_t)slot * HIDDEN * HIDDEN)
                           : (W_self + (size_t)(slot - 3) * HIDDEN * HIDDEN);
        }
        int lane = local & 31;
        int s = (local >> 5) % NSTEP;
        int J = local / (NSTEP * 32);
        int t = lane & 3, g = lane >> 2;
        int k0 = s * 16 + t * 2;
        int k1 = k0 + 8;
        int n = J * 8 + g;
        uint32_t b0 = pack_h2(W[(size_t)k0 * HIDDEN + n], W[(size_t)(k0 + 1) * HIDDEN + n]);
        uint32_t b1 = pack_h2(W[(size_t)k1 * HIDDEN + n], W[(size_t)(k1 + 1) * HIDDEN + n]);
        g_w2[idx] = make_uint2(b0, b1);
    }
}

// ---------------- input projection GEMM (fp32 A -> packed h out) -------------------
__global__ __launch_bounds__(256, 2)
void gemm_in_k(const float* __restrict__ A,
               const uint2* __restrict__ B2,
               const float* __restrict__ bias,
               uint2* __restrict__ Cpk, int M) {
    constexpr int K_ = IN_FEAT, NSTEP = K_ / 16;
    const int tid  = threadIdx.x;
    const int warp = tid >> 5;
    const int lane = tid & 31;
    const int g = lane >> 2, t = lane & 3;
    const int warp_m = (warp & 3) * 32;
    const int warp_n = (warp >> 2) * 64;
    const int row_base = blockIdx.x * 128 + warp_m;

    float acc[2][8][4];
#pragma unroll
    for (int mt = 0; mt < 2; mt++)
#pragma unroll
        for (int j = 0; j < 8; j++)
#pragma unroll
            for (int q = 0; q < 4; q++) acc[mt][j][q] = 0.f;

#pragma unroll
    for (int s = 0; s < NSTEP; s++) {
        uint32_t ahi[2][4], alo[2][4];
        const int c0 = s * 16 + t * 2;
#pragma unroll
        for (int mt = 0; mt < 2; mt++) {
            int r0 = row_base + mt * 16 + g;
            int r1 = r0 + 8;
            float2 v00 = make_float2(0.f, 0.f), v10 = v00, v01 = v00, v11 = v00;
            if (r0 < M) {
                v00 = *(const float2*)(A + (size_t)r0 * K_ + c0);
                v01 = *(const float2*)(A + (size_t)r0 * K_ + c0 + 8);
            }
            if (r1 < M) {
                v10 = *(const float2*)(A + (size_t)r1 * K_ + c0);
                v11 = *(const float2*)(A + (size_t)r1 * K_ + c0 + 8);
            }
            split2h(v00, ahi[mt][0], alo[mt][0]);
            split2h(v10, ahi[mt][1], alo[mt][1]);
            split2h(v01, ahi[mt][2], alo[mt][2]);
            split2h(v11, ahi[mt][3], alo[mt][3]);
        }
#pragma unroll
        for (int j = 0; j < 8; j++) {
            int J = (warp >> 2) * 8 + j;
            uint2 b = B2[(size_t)(J * NSTEP + s) * 32 + lane];
#pragma unroll
            for (int mt = 0; mt < 2; mt++) {
                mma_f16(acc[mt][j], ahi[mt], b.x, b.y);
                mma_f16(acc[mt][j], alo[mt], b.x, b.y);
            }
        }
    }
#pragma unroll
    for (int j = 0; j < 8; j++) {
        int n0 = warp_n + j * 8 + t * 2;
        float2 bv = *(const float2*)(bias + n0);
#pragma unroll
        for (int mt = 0; mt < 2; mt++) {
            int r0 = row_base + mt * 16 + g;
            int r1 = r0 + 8;
            uint32_t h0, l0, h1, l1;
            split2h(make_float2(acc[mt][j][0] + bv.x, acc[mt][j][1] + bv.y), h0, l0);
            split2h(make_float2(acc[mt][j][2] + bv.x, acc[mt][j][3] + bv.y), h1, l1);
            if (r0 < M) Cpk[(size_t)r0 * HPAIRS + (n0 >> 1)] = make_uint2(h0, l0);
            if (r1 < M) Cpk[(size_t)r1 * HPAIRS + (n0 >> 1)] = make_uint2(h1, l1);
        }
    }
}

// ---------------- dual layer GEMM: one launch, grid (391, 2) -----------------------
// blockIdx.y == 0: Tout = A @ Wn   (fp16 out)
// blockIdx.y == 1: Zout = A @ Ws + bias (fp32 out)
__global__ __launch_bounds__(256, 2)
void gemm_layer_k(const uint2* __restrict__ Apk,
                  const uint2* __restrict__ Bn,
                  const uint2* __restrict__ Bs,
                  const float* __restrict__ bias,
                  __half2* __restrict__ Tout,
                  float* __restrict__ Zout, int M) {
    constexpr int NSTEP = HIDDEN / 16;  // 8
    const int tid  = threadIdx.x;
    const int warp = tid >> 5;
    const int lane = tid & 31;
    const int g = lane >> 2, t = lane & 3;
    const int warp_m = (warp & 3) * 32;
    const int warp_n = (warp >> 2) * 64;
    const int row_base = blockIdx.x * 128 + warp_m;
    const bool is_z = (blockIdx.y != 0);
    const uint2* __restrict__ B2 = is_z ? Bs : Bn;

    float acc[2][8][4];
#pragma unroll
    for (int mt = 0; mt < 2; mt++)
#pragma unroll
        for (int j = 0; j < 8; j++)
#pragma unroll
            for (int q = 0; q < 4; q++) acc[mt][j][q] = 0.f;

#pragma unroll
    for (int s = 0; s < NSTEP; s++) {
        uint32_t ahi[2][4], alo[2][4];
        const int pr = s * 8 + t;
#pragma unroll
        for (int mt = 0; mt < 2; mt++) {
            int r0 = row_base + mt * 16 + g;
            int r1 = r0 + 8;
            uint2 zz = make_uint2(0u, 0u);
            uint2 p00 = zz, p01 = zz, p10 = zz, p11 = zz;
            if (r0 < M) {
                p00 = Apk[(size_t)r0 * HPAIRS + pr];
                p01 = Apk[(size_t)r0 * HPAIRS + pr + 4];
            }
            if (r1 < M) {
                p10 = Apk[(size_t)r1 * HPAIRS + pr];
                p11 = Apk[(size_t)r1 * HPAIRS + pr + 4];
            }
            ahi[mt][0] = p00.x; alo[mt][0] = p00.y;
            ahi[mt][1] = p10.x; alo[mt][1] = p10.y;
            ahi[mt][2] = p01.x; alo[mt][2] = p01.y;
            ahi[mt][3] = p11.x; alo[mt][3] = p11.y;
        }
#pragma unroll
        for (int j = 0; j < 8; j++) {
            int J = (warp >> 2) * 8 + j;
            uint2 b = B2[(size_t)(J * NSTEP + s) * 32 + lane];
#pragma unroll
            for (int mt = 0; mt < 2; mt++) {
                mma_f16(acc[mt][j], ahi[mt], b.x, b.y);
                mma_f16(acc[mt][j], alo[mt], b.x, b.y);
            }
        }
    }

    if (is_z) {
#pragma unroll
        for (int j = 0; j < 8; j++) {
            int n0 = warp_n + j * 8 + t * 2;
            float2 bv = *(const float2*)(bias + n0);
#pragma unroll
            for (int mt = 0; mt < 2; mt++) {
                int r0 = row_base + mt * 16 + g;
                int r1 = r0 + 8;
                if (r0 < M)
                    *(float2*)(Zout + (size_t)r0 * HIDDEN + n0) =
                        make_float2(acc[mt][j][0] + bv.x, acc[mt][j][1] + bv.y);
                if (r1 < M)
                    *(float2*)(Zout + (size_t)r1 * HIDDEN + n0) =
                        make_float2(acc[mt][j][2] + bv.x, acc[mt][j][3] + bv.y);
            }
        }
    } else {
#pragma unroll
        for (int j = 0; j < 8; j++) {
            int n0 = warp_n + j * 8 + t * 2;
#pragma unroll
            for (int mt = 0; mt < 2; mt++) {
                int r0 = row_base + mt * 16 + g;
                int r1 = r0 + 8;
                if (r0 < M)
                    Tout[(size_t)r0 * HPAIRS + (n0 >> 1)] =
                        __floats2half2_rn(acc[mt][j][0], acc[mt][j][1]);
                if (r1 < M)
                    Tout[(size_t)r1 * HPAIRS + (n0 >> 1)] =
                        __floats2half2_rn(acc[mt][j][2], acc[mt][j][3]);
            }
        }
    }
}

// ---------------- fused gather + epilogue (t in fp16, 8-wide MLP) -------------------
// r = elu( z[n] + (sum t[src])/max(deg,1) );  LAST: write fp32 out, else packed h
template <int LAST>
__global__ __launch_bounds__(256)
void gather_fused_k(const __half2* __restrict__ t16,
                    const float* __restrict__ z,
                    void* __restrict__ outv) {
    int gtid = blockIdx.x * blockDim.x + threadIdx.x;
    int node = gtid >> 5;
    if (node >= N_NODES) return;
    int lane = gtid & 31;
    int c = lane * 4;               // fp32 column base
    int p = lane * 2;               // half2 pair base

    int start = g_offs[node];
    int end   = g_offs[node + 1];

    float4 acc = make_float4(0.f, 0.f, 0.f, 0.f);
    int e = start;
    // 8-wide: 8 independent row loads in flight
    for (; e + 8 <= end; e += 8) {
        int si[8];
#pragma unroll
        for (int u = 0; u < 8; u++) si[u] = g_esrc[e + u];
        uint2 q[8];
#pragma unroll
        for (int u = 0; u < 8; u++)
            q[u] = __ldg((const uint2*)(t16 + (size_t)si[u] * HPAIRS + p));
#pragma unroll
        for (int u = 0; u < 8; u++) {
            float2 a = __half22float2(*(__half2*)&q[u].x);
            float2 b = __half22float2(*(__half2*)&q[u].y);
            acc.x += a.x; acc.y += a.y; acc.z += b.x; acc.w += b.y;
        }
    }
    for (; e + 4 <= end; e += 4) {
        int si[4];
#pragma unroll
        for (int u = 0; u < 4; u++) si[u] = g_esrc[e + u];
        uint2 q[4];
#pragma unroll
        for (int u = 0; u < 4; u++)
            q[u] = __ldg((const uint2*)(t16 + (size_t)si[u] * HPAIRS + p));
#pragma unroll
        for (int u = 0; u < 4; u++) {
            float2 a = __half22float2(*(__half2*)&q[u].x);
            float2 b = __half22float2(*(__half2*)&q[u].y);
            acc.x += a.x; acc.y += a.y; acc.z += b.x; acc.w += b.y;
        }
    }
    for (; e < end; e++) {
        int s = g_esrc[e];
        uint2 q = __ldg((const uint2*)(t16 + (size_t)s * HPAIRS + p));
        float2 a = __half22float2(*(__half2*)&q.x), b = __half22float2(*(__half2*)&q.y);
        acc.x += a.x; acc.y += a.y; acc.z += b.x; acc.w += b.y;
    }

    float inv = 1.0f / fmaxf((float)(end - start), 1.0f);
    float4 zv = __ldg((const float4*)(z + (size_t)node * HIDDEN + c));
    float4 r;
    r.x = zv.x + acc.x * inv;
    r.y = zv.y + acc.y * inv;
    r.z = zv.z + acc.z * inv;
    r.w = zv.w + acc.w * inv;
    r.x = (r.x > 0.f) ? r.x : expm1f(r.x);
    r.y = (r.y > 0.f) ? r.y : expm1f(r.y);
    r.z = (r.z > 0.f) ? r.z : expm1f(r.z);
    r.w = (r.w > 0.f) ? r.w : expm1f(r.w);

    if (LAST) {
        *(float4*)((float*)outv + (size_t)node * HIDDEN + c) = r;
    } else {
        uint32_t h0, l0, h1, l1;
        split2h(make_float2(r.x, r.y), h0, l0);
        split2h(make_float2(r.z, r.w), h1, l1);
        *(uint4*)((uint2*)outv + (size_t)node * HPAIRS + p) =
            make_uint4(h0, l0, h1, l1);
    }
}

// ---------------- launch ----------------------------------------------------------
extern "C" void kernel_launch(void* const* d_in, const int* in_sizes, int n_in,
                              void* d_out, int out_size) {
    const float* x      = (const float*)d_in[0];
    const int*   ei     = (const int*)d_in[1];
    const float* W_in   = (const float*)d_in[2];
    const float* b_in   = (const float*)d_in[3];
    const float* W_self = (const float*)d_in[4];
    const float* b_self = (const float*)d_in[5];
    const float* W_nbr  = (const float*)d_in[6];
    float*       out    = (float*)d_out;

    uint2*   hpkA; cudaGetSymbolAddress((void**)&hpkA, g_hpkA);
    uint2*   hpkB; cudaGetSymbolAddress((void**)&hpkB, g_hpkB);
    __half2* t16;  cudaGetSymbolAddress((void**)&t16,  g_t16);
    float*   z;    cudaGetSymbolAddress((void**)&z,    g_z);
    int*     cnt;  cudaGetSymbolAddress((void**)&cnt,  g_cnt);
    uint2*   w2;   cudaGetSymbolAddress((void**)&w2,   g_w2);

    const int M = N_NODES;
    const int gemm_blocks = (M + 127) / 128;   // 391

    // ---- CSR build (5 launches) ----
    detect_k<<<1, 32>>>(ei);
    cudaMemsetAsync(cnt, 0, N_NODES * sizeof(int));
    count_k<<<(N_EDGES + 255) / 256, 256>>>(ei);
    scan_fused_k<<<NBLK, 256>>>();
    fill_k<<<(N_EDGES + 255) / 256, 256>>>(ei);

    // ---- all weight packing in one launch ----
    conv_all_k<<<64, 256>>>(W_in, W_nbr, W_self);

    // ---- input projection: hpkA = pack(x @ W_in + b_in) ----
    gemm_in_k<<<gemm_blocks, 256>>>(x, w2, b_in, hpkA, M);

    const uint2* hcur = hpkA;
    for (int l = 0; l < NUM_LAYERS; l++) {
        const float* bs = b_self + (size_t)l * HIDDEN;
        const uint2* wn = w2 + 2048 + l * 4096;
        const uint2* ws = w2 + 2048 + (3 + l) * 4096;
        uint2* hnext = (hcur == hpkA) ? hpkB : hpkA;

        dim3 grid(gemm_blocks, 2);
        gemm_layer_k<<<grid, 256>>>(hcur, wn, ws, bs, t16, z, M);
        if (l == NUM_LAYERS - 1)
            gather_fused_k<1><<<(N_NODES * 32 + 255) / 256, 256>>>(t16, z, out);
        else
            gather_fused_k<0><<<(N_NODES * 32 + 255) / 256, 256>>>(t16, z, hnext);

        hcur = hnext;
    }
}